// round 10
// baseline (speedup 1.0000x reference)
#include <cuda_runtime.h>

// Problem constants (fixed by setup_inputs)
#define LAT    4
#define MM     1024
#define DIM    16
#define PP     16384
#define MTILE  64
#define PTILE  128
#define NMT    (MM / MTILE)      // 16
#define PSPLIT 8
#define PCHUNK (PP / PSPLIT)     // 2048
#define NTILES (PCHUNK / PTILE)  // 16
#define NT     256
#define NBLOCKS (LAT * NMT * PSPLIT)  // 512

typedef unsigned long long u64;

// scratch: partial sums [ps][l][mt][64]
__device__ float    g_part[PSPLIT * LAT * NMT * MTILE];
__device__ unsigned g_ctr = 0;

__device__ __forceinline__ float ex2f(float x) {
    float y;
    asm("ex2.approx.ftz.f32 %0, %1;" : "=f"(y) : "f"(x));
    return y;
}
__device__ __forceinline__ u64 fma2(u64 a, u64 b, u64 c) {
    u64 d;
    asm("fma.rn.f32x2 %0, %1, %2, %3;" : "=l"(d) : "l"(a), "l"(b), "l"(c));
    return d;
}
__device__ __forceinline__ u64 add2(u64 a, u64 b) {
    u64 d;
    asm("add.rn.f32x2 %0, %1, %2;" : "=l"(d) : "l"(a), "l"(b));
    return d;
}
__device__ __forceinline__ void unpack2(u64 v, float& lo, float& hi) {
    asm("mov.b64 {%0, %1}, %2;" : "=f"(lo), "=f"(hi) : "l"(v));
}
// reinterpret a float4 (one LDS.128) as two packed f32x2 operands
__device__ __forceinline__ void as2xu64(const float4 v, u64& lo, u64& hi) {
    asm("mov.b64 %0, {%2, %3}; mov.b64 %1, {%4, %5};"
        : "=l"(lo), "=l"(hi) : "f"(v.x), "f"(v.y), "f"(v.z), "f"(v.w));
}

__global__ __launch_bounds__(NT)
void fused_latent_kernel(const float* __restrict__ z,
                         const float* __restrict__ e,
                         const float* __restrict__ log_sigma,
                         float* __restrict__ out) {
    const int b   = blockIdx.x;
    const int l   = b >> 7;        // 128 blocks per latent
    const int r   = b & 127;
    const int mt  = r >> 3;        // 0..15
    const int ps  = r & 7;         // 0..7
    const int m0  = mt * MTILE;
    const int tid = threadIdx.x;

    // alpha = -0.5*exp(-2*sigma); A = alpha*log2(e); kk = -2A (coef on dot)
    const float sig   = log_sigma[0];
    const float A     = -0.5f * __expf(-2.0f * sig) * 1.4426950408889634f;
    const float kk    = -2.0f * A;
    const float inv4A = 0.25f / A;   // converts ||kk*e||^2 -> A*||e||^2

    __shared__ __align__(16) float  zs[DIM][PTILE];   // z tile, d-major         (8 KB)
    __shared__ __align__(16) float2 es2[DIM][MTILE];  // {kk*e, kk*e} duplicated (8 KB)
    __shared__ __align__(16) float  azsq[PTILE];      // A*||z_p||^2
    __shared__ float2 aesq2[MTILE];                   // {A*||e||^2} duplicated
    __shared__ float  sred[NT];
    __shared__ unsigned is_last;

    // ---- load e' = kk*e, transposed to d-major, duplicated per lane pair ----
    {
        const int m  = tid & 63;
        const int d0 = (tid >> 6) << 2;          // 0,4,8,12
        const float4 ev = *(const float4*)(e + (l * MM + m0 + m) * DIM + d0);
        es2[d0 + 0][m] = make_float2(kk * ev.x, kk * ev.x);
        es2[d0 + 1][m] = make_float2(kk * ev.y, kk * ev.y);
        es2[d0 + 2][m] = make_float2(kk * ev.z, kk * ev.z);
        es2[d0 + 3][m] = make_float2(kk * ev.w, kk * ev.w);
    }
    __syncthreads();
    if (tid < MTILE) {
        float s = 0.f;
        #pragma unroll
        for (int d = 0; d < DIM; ++d) { float v = es2[d][tid].x; s = fmaf(v, v, s); }
        const float ae = s * inv4A;          // A*||e||^2
        aesq2[tid] = make_float2(ae, ae);
    }

    // thread tiling: pi in 0..15 (8 points = 4 f32x2 pairs), mi in 0..15 (4 codes)
    const int pi = tid & 15;
    const int mi = tid >> 4;

    // z tile loader role: row d = tid>>4, two float4 at jld and jld+64
    const int dld = tid >> 4;
    const int jld = (tid & 15) << 2;

    float4 zfA, zfB;
    {
        const int p  = ps * PCHUNK;
        const int n  = p >> 10;
        const int hw = p & 1023;
        const float* zp = z + (((n * 64 + l * DIM + dld) << 10) + hw);
        zfA = *(const float4*)(zp + jld);
        zfB = *(const float4*)(zp + jld + 64);
    }
    __syncthreads();   // aesq2 ready

    u64 ae2[4];
    #pragma unroll
    for (int c = 0; c < 4; ++c)
        ae2[c] = *(const u64*)&aesq2[(mi << 2) + c];

    float msum[4] = {0.f, 0.f, 0.f, 0.f};

    for (int i = 0; i < NTILES; ++i) {
        // stage current tile
        *(float4*)&zs[dld][jld]      = zfA;
        *(float4*)&zs[dld][jld + 64] = zfB;
        __syncthreads();

        // per-point A*||z||^2 (threads 0..127)
        if (tid < PTILE) {
            float s = 0.f;
            #pragma unroll
            for (int d = 0; d < DIM; ++d) { float v = zs[d][tid]; s = fmaf(v, v, s); }
            azsq[tid] = A * s;
        }
        // prefetch next tile (overlaps mainloop)
        if (i + 1 < NTILES) {
            const int p  = ps * PCHUNK + (i + 1) * PTILE;
            const int n  = p >> 10;
            const int hw = p & 1023;
            const float* zp = z + (((n * 64 + l * DIM + dld) << 10) + hw);
            zfA = *(const float4*)(zp + jld);
            zfB = *(const float4*)(zp + jld + 64);
        }
        __syncthreads();

        // 8x4 register tile as 4 f32x2 point-pairs x 4 codes: FFMA2 mainloop
        u64 acc[4][4];
        #pragma unroll
        for (int c = 0; c < 4; ++c)
            #pragma unroll
            for (int pp = 0; pp < 4; ++pp) acc[c][pp] = 0ull;

        #pragma unroll
        for (int d = 0; d < DIM; ++d) {
            // one LDS.128 each -> two packed f32x2 operands
            const float4 zA4 = *(const float4*)&zs[d][pi << 3];
            const float4 zB4 = *(const float4*)&zs[d][(pi << 3) + 4];
            const float4 eA4 = *(const float4*)&es2[d][(mi << 2)];
            const float4 eB4 = *(const float4*)&es2[d][(mi << 2) + 2];
            u64 zA0, zA1, zB0, zB1, eA0, eA1, eB0, eB1;
            as2xu64(zA4, zA0, zA1);
            as2xu64(zB4, zB0, zB1);
            as2xu64(eA4, eA0, eA1);
            as2xu64(eB4, eB0, eB1);
            acc[0][0] = fma2(zA0, eA0, acc[0][0]);
            acc[0][1] = fma2(zA1, eA0, acc[0][1]);
            acc[0][2] = fma2(zB0, eA0, acc[0][2]);
            acc[0][3] = fma2(zB1, eA0, acc[0][3]);
            acc[1][0] = fma2(zA0, eA1, acc[1][0]);
            acc[1][1] = fma2(zA1, eA1, acc[1][1]);
            acc[1][2] = fma2(zB0, eA1, acc[1][2]);
            acc[1][3] = fma2(zB1, eA1, acc[1][3]);
            acc[2][0] = fma2(zA0, eB0, acc[2][0]);
            acc[2][1] = fma2(zA1, eB0, acc[2][1]);
            acc[2][2] = fma2(zB0, eB0, acc[2][2]);
            acc[2][3] = fma2(zB1, eB0, acc[2][3]);
            acc[3][0] = fma2(zA0, eB1, acc[3][0]);
            acc[3][1] = fma2(zA1, eB1, acc[3][1]);
            acc[3][2] = fma2(zB0, eB1, acc[3][2]);
            acc[3][3] = fma2(zB1, eB1, acc[3][3]);
        }

        // packed epilogue: exp2(dot' + A||z||^2 + A||e||^2)
        u64 az2[4];
        {
            const float4 azA = *(const float4*)&azsq[(pi << 3)];
            const float4 azB = *(const float4*)&azsq[(pi << 3) + 4];
            as2xu64(azA, az2[0], az2[1]);
            as2xu64(azB, az2[2], az2[3]);
        }

        #pragma unroll
        for (int c = 0; c < 4; ++c) {
            float s0 = 0.f, s1 = 0.f;
            #pragma unroll
            for (int pp = 0; pp < 4; ++pp) {
                const u64 t = add2(acc[c][pp], add2(az2[pp], ae2[c]));
                float lo, hi;
                unpack2(t, lo, hi);
                s0 += ex2f(lo);
                s1 += ex2f(hi);
            }
            msum[c] += s0 + s1;
        }

        __syncthreads();   // protect zs/azsq before next overwrite
    }

    // reduce msum over the 16 pi-lanes (xor<=8 stays within each 16-lane half)
    #pragma unroll
    for (int c = 0; c < 4; ++c) {
        float v = msum[c];
        v += __shfl_xor_sync(0xffffffffu, v, 8);
        v += __shfl_xor_sync(0xffffffffu, v, 4);
        v += __shfl_xor_sync(0xffffffffu, v, 2);
        v += __shfl_xor_sync(0xffffffffu, v, 1);
        msum[c] = v;
    }
    if (pi == 0) {
        float* gp = g_part + ((ps * LAT + l) * NMT + mt) * MTILE + (mi << 2);
        #pragma unroll
        for (int c = 0; c < 4; ++c) gp[c] = msum[c];
    }

    // ---- last-block finalize ----
    __threadfence();
    if (tid == 0) is_last = (atomicAdd(&g_ctr, 1u) == NBLOCKS - 1u);
    __syncthreads();
    if (!is_last) return;

    float local = 0.f;
    for (int j = tid; j < LAT * MM; j += NT) {
        float s = 0.f;
        #pragma unroll
        for (int p = 0; p < PSPLIT; ++p) s += g_part[p * (LAT * MM) + j];
        local += __logf(s);          // lse[l,m] = ln(sum_p exp(alpha*d2))
    }
    sred[tid] = local;
    __syncthreads();
    for (int st = NT / 2; st > 0; st >>= 1) {
        if (tid < st) sred[tid] += sred[tid + st];
        __syncthreads();
    }
    if (tid == 0) {
        g_ctr = 0;   // reset for next launch / graph replay
        out[0] = -sred[0] / (float)(LAT * MM)
               + 32.0f * (2.0f * sig - 1.0f)
               + logf(16384.0f);
    }
}

extern "C" void kernel_launch(void* const* d_in, const int* in_sizes, int n_in,
                              void* d_out, int out_size) {
    const float* z  = (const float*)d_in[0];
    const float* e  = (const float*)d_in[1];
    const float* ls = (const float*)d_in[2];
    float* out = (float*)d_out;

    fused_latent_kernel<<<NBLOCKS, NT>>>(z, e, ls, out);
}

// round 12
// speedup vs baseline: 2.6340x; 2.6340x over previous
#include <cuda_runtime.h>
#include <cuda_bf16.h>
#include <cstdint>

// Problem constants
#define LAT    4
#define MM     1024
#define DIM    16
#define PP     16384
#define MTILE  64             // codes per CTA (4 warps x m16)
#define PTILE  128            // points per staged tile
#define PSPLIT 8
#define PCHUNK (PP / PSPLIT)  // 2048
#define NITER  (PCHUNK / PTILE)  // 16
#define NT     128
#define NBLOCKS (LAT * (MM / MTILE) * PSPLIT)  // 4*16*8 = 512
#define ZS     136            // padded row stride (words) -> conflict-free LDS

__device__ float    g_part[PSPLIT * LAT * MM];
__device__ unsigned g_ctr = 0;

__device__ __forceinline__ float ex2f(float x) {
    float y; asm("ex2.approx.ftz.f32 %0, %1;" : "=f"(y) : "f"(x)); return y;
}
// pack {low=a, high=b} as bf16x2
__device__ __forceinline__ uint32_t pk2(float a, float b) {
    uint32_t r; asm("cvt.rn.bf16x2.f32 %0, %1, %2;" : "=r"(r) : "f"(b), "f"(a)); return r;
}
__device__ __forceinline__ float bfhi(float v) {
    return __bfloat162float(__float2bfloat16(v));
}
// m16n8k16 row.col bf16 -> f32 accumulate (baseline PTX, fallback HMMA on sm_103)
__device__ __forceinline__ void mma_bf16(float& c0, float& c1, float& c2, float& c3,
                                         uint32_t a0, uint32_t a1, uint32_t a2, uint32_t a3,
                                         uint32_t b0, uint32_t b1) {
    asm volatile("mma.sync.aligned.m16n8k16.row.col.f32.bf16.bf16.f32 "
                 "{%0,%1,%2,%3}, {%4,%5,%6,%7}, {%8,%9}, {%0,%1,%2,%3};"
                 : "+f"(c0), "+f"(c1), "+f"(c2), "+f"(c3)
                 : "r"(a0), "r"(a1), "r"(a2), "r"(a3), "r"(b0), "r"(b1));
}

__global__ __launch_bounds__(NT)
void latent_hmma_kernel(const float* __restrict__ z,
                        const float* __restrict__ e,
                        const float* __restrict__ log_sigma,
                        float* __restrict__ out) {
    __shared__ uint32_t zh_pk[8 * ZS];   // {z[2k],z[2k+1]} hi, [k2][p] stride ZS
    __shared__ uint32_t zl_pk[8 * ZS];   // lo residual
    __shared__ float    azsq[PTILE];     // A*||z_p||^2
    __shared__ float    sred[NT];
    __shared__ unsigned is_last;

    const int b   = blockIdx.x;
    const int l   = b >> 7;          // 0..3
    const int r   = b & 127;
    const int mt  = r >> 3;          // 0..15
    const int ps  = r & 7;           // 0..7
    const int m0  = mt * MTILE;
    const int tid = threadIdx.x;
    const int w   = tid >> 5;        // warp 0..3
    const int ln  = tid & 31;
    const int q   = ln & 3;          // k-quad
    const int cg  = ln >> 2;         // col group 0..7

    const float sig = log_sigma[0];
    const float A   = -0.5f * __expf(-2.0f * sig) * 1.4426950408889634f;
    const float kk  = -2.0f * A;     // positive

    // ---- build A fragments (e rows, hi/lo split) once; rows r0, r0+8 ----
    uint32_t ah0, ah1, ah2, ah3, al0, al1, al2, al3;
    float ae0, ae1;
    {
        const int rr0 = m0 + w * 16 + cg;
        const float* e0 = e + (size_t)(l * MM + rr0) * DIM;
        const float* e1 = e0 + 8 * DIM;
        float v0[DIM], v1[DIM];
        #pragma unroll
        for (int d4 = 0; d4 < 4; ++d4) {
            float4 f0 = *(const float4*)(e0 + d4 * 4);
            float4 f1 = *(const float4*)(e1 + d4 * 4);
            v0[d4*4+0] = f0.x; v0[d4*4+1] = f0.y; v0[d4*4+2] = f0.z; v0[d4*4+3] = f0.w;
            v1[d4*4+0] = f1.x; v1[d4*4+1] = f1.y; v1[d4*4+2] = f1.z; v1[d4*4+3] = f1.w;
        }
        float s0 = 0.f, s1 = 0.f;
        #pragma unroll
        for (int d = 0; d < DIM; ++d) { s0 = fmaf(v0[d], v0[d], s0); s1 = fmaf(v1[d], v1[d], s1); }
        ae0 = A * s0; ae1 = A * s1;

        const int c0 = 2 * q, c8 = 2 * q + 8;
        float h;
        // a0: row r0, cols c0,c0+1 ; a1: row r0+8 ; a2: row r0 cols c8 ; a3: row r0+8
        h = bfhi(v0[c0]);   float h2 = bfhi(v0[c0+1]);
        ah0 = pk2(h, h2);   al0 = pk2(v0[c0]-h, v0[c0+1]-h2);
        h = bfhi(v1[c0]);   h2 = bfhi(v1[c0+1]);
        ah1 = pk2(h, h2);   al1 = pk2(v1[c0]-h, v1[c0+1]-h2);
        h = bfhi(v0[c8]);   h2 = bfhi(v0[c8+1]);
        ah2 = pk2(h, h2);   al2 = pk2(v0[c8]-h, v0[c8+1]-h2);
        h = bfhi(v1[c8]);   h2 = bfhi(v1[c8+1]);
        ah3 = pk2(h, h2);   al3 = pk2(v1[c8]-h, v1[c8+1]-h2);
    }

    const float* zbase = z + (size_t)((l * DIM) << 10);

    float ms0 = 0.f, ms1 = 0.f;

    for (int it = 0; it < NITER; ++it) {
        // ---- stage z tile: thread = one point ----
        {
            const int p  = ps * PCHUNK + it * PTILE + tid;
            const int n  = p >> 10;
            const int hw = p & 1023;
            const float* zp = zbase + ((size_t)(n * 64) << 10) + hw;
            float v[DIM];
            #pragma unroll
            for (int d = 0; d < DIM; ++d) v[d] = zp[(size_t)d << 10];
            float sq = 0.f;
            #pragma unroll
            for (int d = 0; d < DIM; ++d) sq = fmaf(v[d], v[d], sq);
            azsq[tid] = A * sq;
            #pragma unroll
            for (int k2 = 0; k2 < 8; ++k2) {
                const float h0 = bfhi(v[2*k2]), h1 = bfhi(v[2*k2+1]);
                zh_pk[k2 * ZS + tid] = pk2(h0, h1);
                zl_pk[k2 * ZS + tid] = pk2(v[2*k2] - h0, v[2*k2+1] - h1);
            }
        }
        __syncthreads();

        // ---- 16 n-chunks of 8 points; warp covers its 16 m-rows ----
        #pragma unroll 4
        for (int nc = 0; nc < PTILE / 8; ++nc) {
            const int p0 = nc * 8;
            const int pc = p0 + cg;
            const uint32_t bh0 = zh_pk[q * ZS + pc];
            const uint32_t bh1 = zh_pk[(q + 4) * ZS + pc];
            const uint32_t bl0 = zl_pk[q * ZS + pc];
            const uint32_t bl1 = zl_pk[(q + 4) * ZS + pc];

            float c0 = 0.f, c1 = 0.f, c2 = 0.f, c3 = 0.f;
            mma_bf16(c0, c1, c2, c3, ah0, ah1, ah2, ah3, bh0, bh1);
            mma_bf16(c0, c1, c2, c3, al0, al1, al2, al3, bh0, bh1);
            mma_bf16(c0, c1, c2, c3, ah0, ah1, ah2, ah3, bl0, bl1);

            const float2 az = *(const float2*)&azsq[p0 + 2 * q];
            ms0 += ex2f(fmaf(kk, c0, az.x)) + ex2f(fmaf(kk, c1, az.y));
            ms1 += ex2f(fmaf(kk, c2, az.x)) + ex2f(fmaf(kk, c3, az.y));
        }
        __syncthreads();   // protect smem before next staging
    }

    // ---- reduce over the 4 lanes sharing each row, fold exp2(A||e||^2) ----
    ms0 += __shfl_xor_sync(0xffffffffu, ms0, 1);
    ms0 += __shfl_xor_sync(0xffffffffu, ms0, 2);
    ms1 += __shfl_xor_sync(0xffffffffu, ms1, 1);
    ms1 += __shfl_xor_sync(0xffffffffu, ms1, 2);
    if (q == 0) {
        const int mrow = m0 + w * 16 + cg;
        float* gp = g_part + (ps * LAT + l) * MM;
        gp[mrow]     = ms0 * ex2f(ae0);
        gp[mrow + 8] = ms1 * ex2f(ae1);
    }

    // ---- last-block finalize ----
    __threadfence();
    if (tid == 0) is_last = (atomicAdd(&g_ctr, 1u) == NBLOCKS - 1u);
    __syncthreads();
    if (!is_last) return;

    float local = 0.f;
    for (int j = tid; j < LAT * MM; j += NT) {
        float s = 0.f;
        #pragma unroll
        for (int p = 0; p < PSPLIT; ++p) s += g_part[p * (LAT * MM) + j];
        local += __logf(s);
    }
    sred[tid] = local;
    __syncthreads();
    for (int st = NT / 2; st > 0; st >>= 1) {
        if (tid < st) sred[tid] += sred[tid + st];
        __syncthreads();
    }
    if (tid == 0) {
        g_ctr = 0;
        out[0] = -sred[0] / (float)(LAT * MM)
               + 32.0f * (2.0f * sig - 1.0f)
               + logf(16384.0f);
    }
}

extern "C" void kernel_launch(void* const* d_in, const int* in_sizes, int n_in,
                              void* d_out, int out_size) {
    const float* z  = (const float*)d_in[0];
    const float* e  = (const float*)d_in[1];
    const float* ls = (const float*)d_in[2];
    float* out = (float*)d_out;

    latent_hmma_kernel<<<NBLOCKS, NT>>>(z, e, ls, out);
}